// round 12
// baseline (speedup 1.0000x reference)
#include <cuda_runtime.h>
#include <cuda_bf16.h>

typedef unsigned long long ull;

#define NTOK 8192   // B*T
#define DDIM 2048
#define NEXP 8
#define IDIM 6144
#define RDIM 32
#define ERD  256    // NEXP*RDIM

// ---------------- scratch (static device allocations are the sanctioned path) ----
__device__ int   g_idx[NTOK];
__device__ float g_AgT[DDIM * ERD];           // A_gate transposed to [D, E*R]
__device__ float g_AuT[DDIM * ERD];
__device__ float g_tg[NTOK * ERD];            // masked lora activations (gate)
__device__ float g_tu[NTOK * ERD];            // masked lora activations (up)
__device__ float g_G[(size_t)NTOK * IDIM];    // gate pre-activation
__device__ float g_H[(size_t)NTOK * IDIM];    // silu(gate)*up
__device__ float g_logits_scratch[NTOK * NEXP];

// ---------------- f32x2 helpers (Blackwell packed fp32) --------------------------
__device__ __forceinline__ ull pk2(float x, float y) {
    ull r;
    asm("mov.b64 %0, {%1,%2};" : "=l"(r) : "f"(x), "f"(y));
    return r;
}
__device__ __forceinline__ void upk2(ull v, float& x, float& y) {
    asm("mov.b64 {%0,%1}, %2;" : "=f"(x), "=f"(y) : "l"(v));
}
__device__ __forceinline__ void fma2(ull& d, ull a, ull b) {
    asm("fma.rn.f32x2 %0, %1, %2, %0;" : "+l"(d) : "l"(a), "l"(b));
}

// ---------------- router: logits + argmax (first-max, matches jnp.argmax) --------
__global__ void router_kernel(const float* __restrict__ x,
                              const float* __restrict__ rw,
                              int* __restrict__ idx,
                              float* __restrict__ logits) {
    int gwarp = (blockIdx.x * blockDim.x + threadIdx.x) >> 5;
    int lane = threadIdx.x & 31;
    if (gwarp >= NTOK) return;
    const float* xp = x + (size_t)gwarp * DDIM;
    float acc[NEXP];
#pragma unroll
    for (int e = 0; e < NEXP; e++) acc[e] = 0.f;
    for (int d = lane; d < DDIM; d += 32) {
        float xv = xp[d];
        const float4* w4 = reinterpret_cast<const float4*>(rw + (size_t)d * NEXP);
        float4 w0 = w4[0], w1 = w4[1];
        acc[0] += xv * w0.x; acc[1] += xv * w0.y;
        acc[2] += xv * w0.z; acc[3] += xv * w0.w;
        acc[4] += xv * w1.x; acc[5] += xv * w1.y;
        acc[6] += xv * w1.z; acc[7] += xv * w1.w;
    }
#pragma unroll
    for (int e = 0; e < NEXP; e++) {
#pragma unroll
        for (int off = 16; off > 0; off >>= 1)
            acc[e] += __shfl_xor_sync(0xffffffffu, acc[e], off);
    }
    if (lane == 0) {
        int best = 0; float bv = acc[0];
#pragma unroll
        for (int e = 1; e < NEXP; e++)
            if (acc[e] > bv) { bv = acc[e]; best = e; }
        idx[gwarp] = best;
#pragma unroll
        for (int e = 0; e < NEXP; e++) logits[gwarp * NEXP + e] = acc[e];
    }
}

// ---------------- transpose A: [E, D, R] -> [D, E*R] -----------------------------
__global__ void transposeA_kernel(const float* __restrict__ Ag,
                                  const float* __restrict__ Au,
                                  float* __restrict__ AgT,
                                  float* __restrict__ AuT) {
    int i = blockIdx.x * blockDim.x + threadIdx.x;
    if (i >= NEXP * DDIM * RDIM) return;
    int r = i & (RDIM - 1);
    int d = (i >> 5) & (DDIM - 1);   // D*R = 65536 = 2^16, R = 32 = 2^5
    int e = i >> 16;
    int o = d * ERD + e * RDIM + r;
    AgT[o] = Ag[i];
    AuT[o] = Au[i];
}

// ---------------- generic SGEMM (f32x2), 128x128x16 tile, 8x8/thread -------------
// C[M,ND] = concat_K(A1[M,K1], A2[M,K2]) @ concat_K(B1[K1,ND], B2[K2,ND])
// MODE 0: plain store
// MODE 1: out = silu(Gprev) * acc          (fused SwiGLU)
// MODE 3: out = acc masked to token's expert (column block of 32 = expert id)
template<int KTOT, int K1, int ND, int MODE>
__global__ void __launch_bounds__(256)
gemm_kernel(const float* __restrict__ A1,
            const float* __restrict__ A2,
            const float* __restrict__ B1,
            const float* __restrict__ B2,
            const int* __restrict__ idx,
            const float* __restrict__ Gprev,
            float* __restrict__ out) {
    constexpr int BM = 128, BN = 128, BK = 16;
    constexpr int K2 = KTOT - K1;
    // A staged as duplicated (a,a) 64-bit pairs, row padded to 130 (1040B: 16B-aligned,
    // bank-shifted) so inner-loop reads need zero MOVs and stores are conflict-light.
    __shared__ ull   As2[BK][BM + 2];
    __shared__ float Bs[BK][BN];

    const int tid = threadIdx.x;
    const int row0 = blockIdx.y * BM;
    const int col0 = blockIdx.x * BN;
    const int tr = tid >> 4;          // 0..15
    const int tc = tid & 15;          // 0..15

    const int a_r = tid >> 2;         // 0..63
    const int a_c = (tid & 3) << 2;   // 0,4,8,12
    const int b_r = tid >> 5;         // 0..7
    const int b_c = (tid & 31) << 2;  // 0..124

    ull acc[8][4];
#pragma unroll
    for (int i = 0; i < 8; i++)
#pragma unroll
        for (int j = 0; j < 4; j++) acc[i][j] = 0ull;

    float4 aReg[2], bReg[2];

    auto loadAB = [&](int kc) {
#pragma unroll
        for (int it = 0; it < 2; it++) {
            int r = row0 + it * 64 + a_r;
            const float* pa;
            if (K2 == 0 || kc < K1)
                pa = A1 + (size_t)r * K1 + kc + a_c;
            else
                pa = A2 + (size_t)r * K2 + (kc - K1) + a_c;
            aReg[it] = *reinterpret_cast<const float4*>(pa);
        }
#pragma unroll
        for (int it = 0; it < 2; it++) {
            int kr = kc + it * 8 + b_r;
            const float* pb;
            if (K2 == 0 || kc < K1)
                pb = B1 + (size_t)kr * ND + col0 + b_c;
            else
                pb = B2 + (size_t)(kr - K1) * ND + col0 + b_c;
            bReg[it] = *reinterpret_cast<const float4*>(pb);
        }
    };

    loadAB(0);

    for (int kc = 0;;) {
        // commit prefetched tiles to smem
#pragma unroll
        for (int it = 0; it < 2; it++) {
            int r = it * 64 + a_r;
            As2[a_c + 0][r] = pk2(aReg[it].x, aReg[it].x);
            As2[a_c + 1][r] = pk2(aReg[it].y, aReg[it].y);
            As2[a_c + 2][r] = pk2(aReg[it].z, aReg[it].z);
            As2[a_c + 3][r] = pk2(aReg[it].w, aReg[it].w);
            *reinterpret_cast<float4*>(&Bs[it * 8 + b_r][b_c]) = bReg[it];
        }
        __syncthreads();

        int knext = kc + BK;
        if (knext < KTOT) loadAB(knext);

#pragma unroll
        for (int k = 0; k < BK; k++) {
            ulonglong2 aq0 = *reinterpret_cast<const ulonglong2*>(&As2[k][tr * 4]);
            ulonglong2 aq1 = *reinterpret_cast<const ulonglong2*>(&As2[k][tr * 4 + 2]);
            ulonglong2 aq2 = *reinterpret_cast<const ulonglong2*>(&As2[k][64 + tr * 4]);
            ulonglong2 aq3 = *reinterpret_cast<const ulonglong2*>(&As2[k][64 + tr * 4 + 2]);
            ulonglong2 bq0 = *reinterpret_cast<const ulonglong2*>(&Bs[k][tc * 4]);
            ulonglong2 bq1 = *reinterpret_cast<const ulonglong2*>(&Bs[k][64 + tc * 4]);
            ull a2[8] = {aq0.x, aq0.y, aq1.x, aq1.y, aq2.x, aq2.y, aq3.x, aq3.y};
            ull b2[4] = {bq0.x, bq0.y, bq1.x, bq1.y};
#pragma unroll
            for (int i = 0; i < 8; i++)
#pragma unroll
                for (int j = 0; j < 4; j++) fma2(acc[i][j], a2[i], b2[j]);
        }

        if (knext >= KTOT) break;
        __syncthreads();
        kc = knext;
    }

    // epilogue
    const int cbase0 = col0 + tc * 4;
    const int cbase1 = col0 + 64 + tc * 4;
    const int ce0 = cbase0 >> 5;    // expert id of column block (MODE 3)
    const int ce1 = cbase1 >> 5;

#pragma unroll
    for (int i = 0; i < 8; i++) {
        int row = row0 + (i < 4 ? tr * 4 + i : 64 + tr * 4 + (i - 4));
        float c[8];
        upk2(acc[i][0], c[0], c[1]);
        upk2(acc[i][1], c[2], c[3]);
        upk2(acc[i][2], c[4], c[5]);
        upk2(acc[i][3], c[6], c[7]);
        size_t base0 = (size_t)row * ND + cbase0;
        size_t base1 = (size_t)row * ND + cbase1;
        if (MODE == 3) {
            int e = idx[row];
            float k0 = (e == ce0) ? 1.f : 0.f;
            float k1 = (e == ce1) ? 1.f : 0.f;
#pragma unroll
            for (int j = 0; j < 4; j++) { c[j] *= k0; c[4 + j] *= k1; }
        }
        if (MODE == 1) {
#pragma unroll
            for (int j = 0; j < 4; j++) {
                float g = Gprev[base0 + j];
                c[j] *= g / (1.f + __expf(-g));
            }
#pragma unroll
            for (int j = 0; j < 4; j++) {
                float g = Gprev[base1 + j];
                c[4 + j] *= g / (1.f + __expf(-g));
            }
        }
        *reinterpret_cast<float4*>(out + base0) = make_float4(c[0], c[1], c[2], c[3]);
        *reinterpret_cast<float4*>(out + base1) = make_float4(c[4], c[5], c[6], c[7]);
    }
}

// ---------------- launch ----------------------------------------------------------
extern "C" void kernel_launch(void* const* d_in, const int* in_sizes, int n_in,
                              void* d_out, int out_size) {
    const float* x  = (const float*)d_in[0];
    const float* rw = (const float*)d_in[1];
    const float* Ag = (const float*)d_in[2];
    const float* Bg = (const float*)d_in[3];   // [E,R,I] == [256, 6144]
    const float* Au = (const float*)d_in[4];
    const float* Bu = (const float*)d_in[5];
    const float* Wg = (const float*)d_in[6];
    const float* Wu = (const float*)d_in[7];
    const float* Wd = (const float*)d_in[8];
    float* out = (float*)d_out;

    void* p;
    cudaGetSymbolAddress(&p, g_idx);            int*   idx = (int*)p;
    cudaGetSymbolAddress(&p, g_AgT);            float* AgT = (float*)p;
    cudaGetSymbolAddress(&p, g_AuT);            float* AuT = (float*)p;
    cudaGetSymbolAddress(&p, g_tg);             float* tg  = (float*)p;
    cudaGetSymbolAddress(&p, g_tu);             float* tu  = (float*)p;
    cudaGetSymbolAddress(&p, g_G);              float* G   = (float*)p;
    cudaGetSymbolAddress(&p, g_H);              float* H   = (float*)p;
    cudaGetSymbolAddress(&p, g_logits_scratch); float* lsc = (float*)p;

    const long long down_elems = (long long)NTOK * DDIM;   // 16,777,216
    float* logits = ((long long)out_size >= down_elems + (long long)NTOK * NEXP)
                        ? (out + down_elems) : lsc;

    // 1. A_{gate,up}: [E,D,R] -> [D, E*R]
    transposeA_kernel<<<(NEXP * DDIM * RDIM + 255) / 256, 256>>>(Ag, Au, AgT, AuT);
    // 2. router logits + top-1 index
    router_kernel<<<NTOK / 8, 256>>>(x, rw, idx, logits);
    // 3. masked LoRA activations: t = x @ A_T, zeroed outside selected expert block
    gemm_kernel<DDIM, DDIM, ERD, 3>
        <<<dim3(ERD / 128, NTOK / 128), 256>>>(x, nullptr, AgT, nullptr, idx, nullptr, tg);
    gemm_kernel<DDIM, DDIM, ERD, 3>
        <<<dim3(ERD / 128, NTOK / 128), 256>>>(x, nullptr, AuT, nullptr, idx, nullptr, tu);
    // 4. gate = [x | tg] @ [W_gate ; B_gate]   (K = 2304)
    gemm_kernel<DDIM + ERD, DDIM, IDIM, 0>
        <<<dim3(IDIM / 128, NTOK / 128), 256>>>(x, tg, Wg, Bg, nullptr, nullptr, G);
    // 5. H = silu(gate) * ([x | tu] @ [W_up ; B_up])
    gemm_kernel<DDIM + ERD, DDIM, IDIM, 1>
        <<<dim3(IDIM / 128, NTOK / 128), 256>>>(x, tu, Wu, Bu, nullptr, G, H);
    // 6. down = H @ W_down
    gemm_kernel<IDIM, IDIM, DDIM, 0>
        <<<dim3(DDIM / 128, NTOK / 128), 256>>>(H, nullptr, Wd, nullptr, nullptr, nullptr, out);
}

// round 15
// speedup vs baseline: 2.2990x; 2.2990x over previous
#include <cuda_runtime.h>
#include <cuda_bf16.h>

typedef unsigned long long ull;
typedef unsigned int u32;
typedef unsigned long long u64;
typedef __nv_bfloat16 bf16;

#define NTOK 8192   // B*T
#define DDIM 2048
#define NEXP 8
#define IDIM 6144
#define RDIM 32
#define ERD  256    // NEXP*RDIM
#define KGATE (DDIM + ERD)   // 2304

// ---------------- scratch ---------------------------------------------------------
__device__ int   g_idx[NTOK];
__device__ float g_AgT[DDIM * ERD];
__device__ float g_AuT[DDIM * ERD];
__device__ float g_G[(size_t)NTOK * IDIM];
__device__ float g_logits_scratch[NTOK * NEXP];
// bf16 hi/lo operands
__device__ bf16 g_xh[(size_t)NTOK * DDIM];
__device__ bf16 g_xl[(size_t)NTOK * DDIM];
__device__ bf16 g_tgh[NTOK * ERD];
__device__ bf16 g_tgl[NTOK * ERD];
__device__ bf16 g_tuh[NTOK * ERD];
__device__ bf16 g_tul[NTOK * ERD];
__device__ bf16 g_Hh[(size_t)NTOK * IDIM];
__device__ bf16 g_Hl[(size_t)NTOK * IDIM];
// transposed + hi/lo-split weights: [N, Ktot] K-major
__device__ bf16 g_WgTh[(size_t)IDIM * KGATE];
__device__ bf16 g_WgTl[(size_t)IDIM * KGATE];
__device__ bf16 g_WuTh[(size_t)IDIM * KGATE];
__device__ bf16 g_WuTl[(size_t)IDIM * KGATE];
__device__ bf16 g_WdTh[(size_t)DDIM * IDIM];
__device__ bf16 g_WdTl[(size_t)DDIM * IDIM];

// ---------------- helpers ---------------------------------------------------------
__device__ __forceinline__ u32 s2u(const void* p) {
    u32 a;
    asm("{ .reg .u64 t; cvta.to.shared.u64 t, %1; cvt.u32.u64 %0, t; }" : "=r"(a) : "l"(p));
    return a;
}
// pack two fp32 -> bf16x2 (a -> low half, b -> high half)
__device__ __forceinline__ u32 cvt2(float a, float b) {
    u32 r;
    asm("cvt.rn.bf16x2.f32 %0, %1, %2;" : "=r"(r) : "f"(b), "f"(a));
    return r;
}
// split 2 floats into hi bf16x2 + lo bf16x2
__device__ __forceinline__ void split2(float a, float b, u32& h, u32& l) {
    h = cvt2(a, b);
    float fa = __uint_as_float(h << 16);
    float fb = __uint_as_float(h & 0xffff0000u);
    l = cvt2(a - fa, b - fb);
}
__device__ __forceinline__ void cpa(u32 d, const void* s) {
    asm volatile("cp.async.cg.shared.global [%0], [%1], 16;" :: "r"(d), "l"(s));
}
__device__ __forceinline__ void cp_commit() {
    asm volatile("cp.async.commit_group;" ::: "memory");
}
__device__ __forceinline__ void cp_wait1() {
    asm volatile("cp.async.wait_group 1;" ::: "memory");
}
__device__ __forceinline__ void ldm_x4(u32& r0, u32& r1, u32& r2, u32& r3, u32 a) {
    asm volatile("ldmatrix.sync.aligned.m8n8.x4.shared.b16 {%0,%1,%2,%3}, [%4];"
                 : "=r"(r0), "=r"(r1), "=r"(r2), "=r"(r3) : "r"(a));
}
__device__ __forceinline__ void mma_bf16(float* d, const u32* a, u32 b0, u32 b1) {
    asm volatile(
        "mma.sync.aligned.m16n8k16.row.col.f32.bf16.bf16.f32 "
        "{%0,%1,%2,%3}, {%4,%5,%6,%7}, {%8,%9}, {%0,%1,%2,%3};"
        : "+f"(d[0]), "+f"(d[1]), "+f"(d[2]), "+f"(d[3])
        : "r"(a[0]), "r"(a[1]), "r"(a[2]), "r"(a[3]), "r"(b0), "r"(b1));
}

// ---------------- router ----------------------------------------------------------
__global__ void router_kernel(const float* __restrict__ x,
                              const float* __restrict__ rw,
                              int* __restrict__ idx,
                              float* __restrict__ logits) {
    int gwarp = (blockIdx.x * blockDim.x + threadIdx.x) >> 5;
    int lane = threadIdx.x & 31;
    if (gwarp >= NTOK) return;
    const float* xp = x + (size_t)gwarp * DDIM;
    float acc[NEXP];
#pragma unroll
    for (int e = 0; e < NEXP; e++) acc[e] = 0.f;
    for (int d = lane; d < DDIM; d += 32) {
        float xv = xp[d];
        const float4* w4 = reinterpret_cast<const float4*>(rw + (size_t)d * NEXP);
        float4 w0 = w4[0], w1 = w4[1];
        acc[0] += xv * w0.x; acc[1] += xv * w0.y;
        acc[2] += xv * w0.z; acc[3] += xv * w0.w;
        acc[4] += xv * w1.x; acc[5] += xv * w1.y;
        acc[6] += xv * w1.z; acc[7] += xv * w1.w;
    }
#pragma unroll
    for (int e = 0; e < NEXP; e++) {
#pragma unroll
        for (int off = 16; off > 0; off >>= 1)
            acc[e] += __shfl_xor_sync(0xffffffffu, acc[e], off);
    }
    if (lane == 0) {
        int best = 0; float bv = acc[0];
#pragma unroll
        for (int e = 1; e < NEXP; e++)
            if (acc[e] > bv) { bv = acc[e]; best = e; }
        idx[gwarp] = best;
#pragma unroll
        for (int e = 0; e < NEXP; e++) logits[gwarp * NEXP + e] = acc[e];
    }
}

// ---------------- transpose A: [E, D, R] -> [D, E*R] ------------------------------
__global__ void transposeA_kernel(const float* __restrict__ Ag,
                                  const float* __restrict__ Au,
                                  float* __restrict__ AgT,
                                  float* __restrict__ AuT) {
    int i = blockIdx.x * blockDim.x + threadIdx.x;
    if (i >= NEXP * DDIM * RDIM) return;
    int r = i & (RDIM - 1);
    int d = (i >> 5) & (DDIM - 1);
    int e = i >> 16;
    int o = d * ERD + e * RDIM + r;
    AgT[o] = Ag[i];
    AuT[o] = Au[i];
}

// ------------ weight transpose + bf16 hi/lo split: src [K,N] -> dst [N,Ktot] ------
__global__ void tconv_kernel(const float* __restrict__ src, int N, int ktot, int koff,
                             bf16* __restrict__ dh, bf16* __restrict__ dl) {
    __shared__ float t[32][33];
    int n0 = blockIdx.x * 32, k0 = blockIdx.y * 32;
    int tx = threadIdx.x, ty = threadIdx.y;   // 32 x 8
#pragma unroll
    for (int j = 0; j < 32; j += 8)
        t[ty + j][tx] = src[(size_t)(k0 + ty + j) * N + n0 + tx];
    __syncthreads();
#pragma unroll
    for (int j = 0; j < 32; j += 8) {
        int n = n0 + ty + j, k = k0 + tx;
        float v = t[tx][ty + j];
        bf16 h = __float2bfloat16(v);
        float hf = __bfloat162float(h);
        bf16 l = __float2bfloat16(v - hf);
        size_t o = (size_t)n * ktot + koff + k;
        dh[o] = h; dl[o] = l;
    }
}

// ---------------- convert x fp32 -> bf16 hi/lo -----------------------------------
__global__ void cvt_x_kernel(const float4* __restrict__ src,
                             u32* __restrict__ dh, u32* __restrict__ dl) {
    int i = blockIdx.x * blockDim.x + threadIdx.x;  // group of 4 elements
    float4 v = src[i];
    u32 h0, l0, h1, l1;
    split2(v.x, v.y, h0, l0);
    split2(v.z, v.w, h1, l1);
    dh[i * 2] = h0; dh[i * 2 + 1] = h1;
    dl[i * 2] = l0; dl[i * 2 + 1] = l1;
}

// ---------------- f32x2 helpers for the small LoRA GEMM ---------------------------
__device__ __forceinline__ ull pk2(float x, float y) {
    ull r; asm("mov.b64 %0, {%1,%2};" : "=l"(r) : "f"(x), "f"(y)); return r;
}
__device__ __forceinline__ void upk2(ull v, float& x, float& y) {
    asm("mov.b64 {%0,%1}, %2;" : "=f"(x), "=f"(y) : "l"(v));
}
__device__ __forceinline__ void fma2(ull& d, ull a, ull b) {
    asm("fma.rn.f32x2 %0, %1, %2, %0;" : "+l"(d) : "l"(a), "l"(b));
}

// ------- small LoRA GEMM (f32x2), t = x @ A_T, masked, bf16 hi/lo output ---------
__global__ void __launch_bounds__(256)
lora_gemm_kernel(const float* __restrict__ A1, const float* __restrict__ B1,
                 const int* __restrict__ idx,
                 bf16* __restrict__ oh, bf16* __restrict__ ol) {
    constexpr int KTOT = DDIM, ND = ERD, BM = 128, BK = 16;
    __shared__ ull   As2[BK][BM + 2];
    __shared__ float Bs[BK][128];

    const int tid = threadIdx.x;
    const int row0 = blockIdx.y * BM;
    const int col0 = blockIdx.x * 128;
    const int tr = tid >> 4;
    const int tc = tid & 15;
    const int a_r = tid >> 2;
    const int a_c = (tid & 3) << 2;
    const int b_r = tid >> 5;
    const int b_c = (tid & 31) << 2;

    ull acc[8][4];
#pragma unroll
    for (int i = 0; i < 8; i++)
#pragma unroll
        for (int j = 0; j < 4; j++) acc[i][j] = 0ull;

    float4 aReg[2], bReg[2];
    auto loadAB = [&](int kc) {
#pragma unroll
        for (int it = 0; it < 2; it++) {
            int r = row0 + it * 64 + a_r;
            aReg[it] = *reinterpret_cast<const float4*>(A1 + (size_t)r * KTOT + kc + a_c);
        }
#pragma unroll
        for (int it = 0; it < 2; it++) {
            int kr = kc + it * 8 + b_r;
            bReg[it] = *reinterpret_cast<const float4*>(B1 + (size_t)kr * ND + col0 + b_c);
        }
    };
    loadAB(0);

    for (int kc = 0;;) {
#pragma unroll
        for (int it = 0; it < 2; it++) {
            int r = it * 64 + a_r;
            As2[a_c + 0][r] = pk2(aReg[it].x, aReg[it].x);
            As2[a_c + 1][r] = pk2(aReg[it].y, aReg[it].y);
            As2[a_c + 2][r] = pk2(aReg[it].z, aReg[it].z);
            As2[a_c + 3][r] = pk2(aReg[it].w, aReg[it].w);
            *reinterpret_cast<float4*>(&Bs[it * 8 + b_r][b_c]) = bReg[it];
        }
        __syncthreads();
        int knext = kc + BK;
        if (knext < KTOT) loadAB(knext);
#pragma unroll
        for (int k = 0; k < BK; k++) {
            ulonglong2 aq0 = *reinterpret_cast<const ulonglong2*>(&As2[k][tr * 4]);
            ulonglong2 aq1 = *reinterpret_cast<const ulonglong2*>(&As2[k][tr * 4 + 2]);
            ulonglong2 aq2 = *reinterpret_cast<const ulonglong2*>(&As2[k][64 + tr * 4]);
            ulonglong2 aq3 = *reinterpret_cast<const ulonglong2*>(&As2[k][64 + tr * 4 + 2]);
            ulonglong2 bq0 = *reinterpret_cast<const ulonglong2*>(&Bs[k][tc * 4]);
            ulonglong2 bq1 = *reinterpret_cast<const ulonglong2*>(&Bs[k][64 + tc * 4]);
            ull a2[8] = {aq0.x, aq0.y, aq1.x, aq1.y, aq2.x, aq2.y, aq3.x, aq3.y};
            ull b2[4] = {bq0.x, bq0.y, bq1.x, bq1.y};
#pragma unroll
            for (int i = 0; i < 8; i++)
#pragma unroll
                for (int j = 0; j < 4; j++) fma2(acc[i][j], a2[i], b2[j]);
        }
        if (knext >= KTOT) break;
        __syncthreads();
        kc = knext;
    }

    const int cbase0 = col0 + tc * 4;
    const int cbase1 = col0 + 64 + tc * 4;
    const int ce0 = cbase0 >> 5;
    const int ce1 = cbase1 >> 5;
#pragma unroll
    for (int i = 0; i < 8; i++) {
        int row = row0 + (i < 4 ? tr * 4 + i : 64 + tr * 4 + (i - 4));
        float c[8];
        upk2(acc[i][0], c[0], c[1]);
        upk2(acc[i][1], c[2], c[3]);
        upk2(acc[i][2], c[4], c[5]);
        upk2(acc[i][3], c[6], c[7]);
        int e = idx[row];
        float k0 = (e == ce0) ? 1.f : 0.f;
        float k1 = (e == ce1) ? 1.f : 0.f;
#pragma unroll
        for (int j = 0; j < 4; j++) { c[j] *= k0; c[4 + j] *= k1; }
        size_t base0 = (size_t)row * ND + cbase0;
        size_t base1 = (size_t)row * ND + cbase1;
        u32 h0, l0, h1, l1;
        split2(c[0], c[1], h0, l0);
        split2(c[2], c[3], h1, l1);
        *reinterpret_cast<uint2*>(oh + base0) = make_uint2(h0, h1);
        *reinterpret_cast<uint2*>(ol + base0) = make_uint2(l0, l1);
        split2(c[4], c[5], h0, l0);
        split2(c[6], c[7], h1, l1);
        *reinterpret_cast<uint2*>(oh + base1) = make_uint2(h0, h1);
        *reinterpret_cast<uint2*>(ol + base1) = make_uint2(l0, l1);
    }
}

// ---------------- bf16x3 GEMM on mma.sync (HMMA) ---------------------------------
// C[M, ND] = concat_K(A1[M,K1], A2[M,KTOT-K1]) @ B^T.  All operands bf16 hi/lo.
// MODE 0: store fp32 to outF.   MODE 1: v = silu(Gprev)*acc, store bf16 hi/lo.
// CTA 128x128, 256 thr (8 warps = 2M x 4N, warp tile 64x32), BK=32, 3-stage cp.async.
#define MM_STAGE 40960
#define MM_SMEM  (3 * MM_STAGE)   // 120 KB

template<int KTOT, int K1, int ND, int MODE>
__global__ void __launch_bounds__(256, 1)
mma_gemm(const bf16* __restrict__ A1h, const bf16* __restrict__ A1l,
         const bf16* __restrict__ A2h, const bf16* __restrict__ A2l,
         const bf16* __restrict__ Bh,  const bf16* __restrict__ Bl,
         const float* __restrict__ Gprev,
         float* __restrict__ outF, bf16* __restrict__ outH, bf16* __restrict__ outL) {
    constexpr int NC = KTOT / 32;
    extern __shared__ __align__(128) char smem[];
    const u32 sb = s2u(smem);
    const int tid = threadIdx.x, lane = tid & 31, wid = tid >> 5;
    const int warp_m = wid >> 2, warp_n = wid & 3;
    const int row0 = blockIdx.y * 128, col0 = blockIdx.x * 128;

    // per-thread ldmatrix offsets (row stride 80B)
    // A (m16k16 per ldmatrix.x4): lanes 0-15 -> rows 0-15 byte 0, lanes 16-31 -> +16B
    const u32 aoff = (u32)((warp_m * 64 + (lane & 15)) * 80 + ((lane >> 4) << 4));
    // B (n16k16 per ldmatrix.x4, NON-trans): lanes 0-7 n0-7/k0-7, 8-15 n0-7/k8-15,
    //                                        16-23 n8-15/k0-7, 24-31 n8-15/k8-15
    const u32 boff = (u32)((warp_n * 32 + (lane & 7) + ((lane >> 4) << 3)) * 80
                           + (((lane >> 3) & 1) << 4));

    float acc[4][4][4];
#pragma unroll
    for (int a = 0; a < 4; a++)
#pragma unroll
        for (int b = 0; b < 4; b++)
#pragma unroll
            for (int r = 0; r < 4; r++) acc[a][b][r] = 0.f;

    auto load_stage = [&](int c) {
        int kc = c * 32;
        const bf16 *ah, *al; int kst, ac;
        if (K1 == KTOT || kc < K1) { ah = A1h; al = A1l; kst = K1; ac = kc; }
        else { ah = A2h; al = A2l; kst = KTOT - K1; ac = kc - K1; }
        u32 st = sb + (u32)(c % 3) * MM_STAGE;
#pragma unroll
        for (int i = 0; i < 2; i++) {
            int ci = tid + i * 256, r = ci >> 2, q = ci & 3;
            u32 d = st + (u32)(r * 80 + q * 16);
            size_t go = (size_t)(row0 + r) * kst + ac + q * 8;
            cpa(d,         ah + go);
            cpa(d + 10240, al + go);
            size_t gb = (size_t)(col0 + r) * KTOT + kc + q * 8;
            cpa(d + 20480, Bh + gb);
            cpa(d + 30720, Bl + gb);
        }
    };

    load_stage(0); cp_commit();
    load_stage(1); cp_commit();

    for (int c = 0; c < NC; c++) {
        cp_wait1();
        __syncthreads();
        if (c + 2 < NC) load_stage(c + 2);
        cp_commit();

        u32 st = sb + (u32)(c % 3) * MM_STAGE;
#pragma unroll
        for (int kk = 0; kk < 2; kk++) {
            u32 afh[4][4], afl[4][4], bfh[2][4], bfl[2][4];
#pragma unroll
            for (int mt = 0; mt < 4; mt++) {
                u32 a = st + aoff + (u32)(mt * 16 * 80 + kk * 32);
                ldm_x4(afh[mt][0], afh[mt][1], afh[mt][2], afh[mt][3], a);
                ldm_x4(afl[mt][0], afl[mt][1], afl[mt][2], afl[mt][3], a + 10240);
            }
#pragma unroll
            for (int nt = 0; nt < 2; nt++) {
                u32 b = st + 20480 + boff + (u32)(nt * 16 * 80 + kk * 32);
                ldm_x4(bfh[nt][0], bfh[nt][1], bfh[nt][2], bfh[nt][3], b);
                ldm_x4(bfl[nt][0], bfl[nt][1], bfl[nt][2], bfl[nt][3], b + 10240);
            }
#pragma unroll
            for (int mt = 0; mt < 4; mt++)
#pragma unroll
                for (int nt = 0; nt < 2; nt++) {
                    mma_bf16(acc[mt][nt * 2 + 0], afh[mt], bfh[nt][0], bfh[nt][1]);
                    mma_bf16(acc[mt][nt * 2 + 1], afh[mt], bfh[nt][2], bfh[nt][3]);
                    mma_bf16(acc[mt][nt * 2 + 0], afh[mt], bfl[nt][0], bfl[nt][1]);
                    mma_bf16(acc[mt][nt * 2 + 1], afh[mt], bfl[nt][2], bfl[nt][3]);
                    mma_bf16(acc[mt][nt * 2 + 0], afl[mt], bfh[nt][0], bfh[nt][1]);
                    mma_bf16(acc[mt][nt * 2 + 1], afl[mt], bfh[nt][2], bfh[nt][3]);
                }
        }
    }

    // epilogue
    const int rw0 = row0 + warp_m * 64 + (lane >> 2);
    const int cw0 = col0 + warp_n * 32 + (lane & 3) * 2;
#pragma unroll
    for (int mt = 0; mt < 4; mt++)
#pragma unroll
        for (int n8 = 0; n8 < 4; n8++) {
            float* d = acc[mt][n8];
            int row = rw0 + mt * 16;
            int col = cw0 + n8 * 8;
#pragma unroll
            for (int h = 0; h < 2; h++) {   // h=0: rows r, h=1: r+8
                int rr = row + h * 8;
                float v0 = d[h * 2 + 0], v1 = d[h * 2 + 1];
                size_t o = (size_t)rr * ND + col;
                if (MODE == 0) {
                    *reinterpret_cast<float2*>(outF + o) = make_float2(v0, v1);
                } else {
                    float2 g = *reinterpret_cast<const float2*>(Gprev + o);
                    v0 *= g.x / (1.f + __expf(-g.x));
                    v1 *= g.y / (1.f + __expf(-g.y));
                    u32 hh, ll;
                    split2(v0, v1, hh, ll);
                    *reinterpret_cast<u32*>(outH + o) = hh;
                    *reinterpret_cast<u32*>(outL + o) = ll;
                }
            }
        }
}

// ---------------- launch ----------------------------------------------------------
extern "C" void kernel_launch(void* const* d_in, const int* in_sizes, int n_in,
                              void* d_out, int out_size) {
    const float* x  = (const float*)d_in[0];
    const float* rw = (const float*)d_in[1];
    const float* Ag = (const float*)d_in[2];
    const float* Bg = (const float*)d_in[3];   // [E,R,I] == [256, 6144]
    const float* Au = (const float*)d_in[4];
    const float* Bu = (const float*)d_in[5];
    const float* Wg = (const float*)d_in[6];
    const float* Wu = (const float*)d_in[7];
    const float* Wd = (const float*)d_in[8];
    float* out = (float*)d_out;

    void* p;
    cudaGetSymbolAddress(&p, g_idx);            int*   idx = (int*)p;
    cudaGetSymbolAddress(&p, g_AgT);            float* AgT = (float*)p;
    cudaGetSymbolAddress(&p, g_AuT);            float* AuT = (float*)p;
    cudaGetSymbolAddress(&p, g_G);              float* G   = (float*)p;
    cudaGetSymbolAddress(&p, g_logits_scratch); float* lsc = (float*)p;
    cudaGetSymbolAddress(&p, g_xh);   bf16* xh  = (bf16*)p;
    cudaGetSymbolAddress(&p, g_xl);   bf16* xl  = (bf16*)p;
    cudaGetSymbolAddress(&p, g_tgh);  bf16* tgh = (bf16*)p;
    cudaGetSymbolAddress(&p, g_tgl);  bf16* tgl = (bf16*)p;
    cudaGetSymbolAddress(&p, g_tuh);  bf16* tuh = (bf16*)p;
    cudaGetSymbolAddress(&p, g_tul);  bf16* tul = (bf16*)p;
    cudaGetSymbolAddress(&p, g_Hh);   bf16* Hh  = (bf16*)p;
    cudaGetSymbolAddress(&p, g_Hl);   bf16* Hl  = (bf16*)p;
    cudaGetSymbolAddress(&p, g_WgTh); bf16* WgTh = (bf16*)p;
    cudaGetSymbolAddress(&p, g_WgTl); bf16* WgTl = (bf16*)p;
    cudaGetSymbolAddress(&p, g_WuTh); bf16* WuTh = (bf16*)p;
    cudaGetSymbolAddress(&p, g_WuTl); bf16* WuTl = (bf16*)p;
    cudaGetSymbolAddress(&p, g_WdTh); bf16* WdTh = (bf16*)p;
    cudaGetSymbolAddress(&p, g_WdTl); bf16* WdTl = (bf16*)p;

    const long long down_elems = (long long)NTOK * DDIM;
    float* logits = ((long long)out_size >= down_elems + (long long)NTOK * NEXP)
                        ? (out + down_elems) : lsc;

    cudaFuncSetAttribute(mma_gemm<KGATE, DDIM, IDIM, 0>,
                         cudaFuncAttributeMaxDynamicSharedMemorySize, MM_SMEM);
    cudaFuncSetAttribute(mma_gemm<KGATE, DDIM, IDIM, 1>,
                         cudaFuncAttributeMaxDynamicSharedMemorySize, MM_SMEM);
    cudaFuncSetAttribute(mma_gemm<IDIM, IDIM, DDIM, 0>,
                         cudaFuncAttributeMaxDynamicSharedMemorySize, MM_SMEM);

    // weight prep: transpose + hi/lo split into combined [N, Ktot]
    dim3 tb32(32, 8);
    tconv_kernel<<<dim3(IDIM / 32, DDIM / 32), tb32>>>(Wg, IDIM, KGATE, 0,    WgTh, WgTl);
    tconv_kernel<<<dim3(IDIM / 32, ERD  / 32), tb32>>>(Bg, IDIM, KGATE, DDIM, WgTh, WgTl);
    tconv_kernel<<<dim3(IDIM / 32, DDIM / 32), tb32>>>(Wu, IDIM, KGATE, 0,    WuTh, WuTl);
    tconv_kernel<<<dim3(IDIM / 32, ERD  / 32), tb32>>>(Bu, IDIM, KGATE, DDIM, WuTh, WuTl);
    tconv_kernel<<<dim3(DDIM / 32, IDIM / 32), tb32>>>(Wd, DDIM, IDIM,  0,    WdTh, WdTl);

    // activations: x -> bf16 hi/lo
    cvt_x_kernel<<<(NTOK * DDIM / 4) / 256, 256>>>(
        reinterpret_cast<const float4*>(x), (u32*)xh, (u32*)xl);

    // router + lora (fp32 compute, bf16 hi/lo output)
    transposeA_kernel<<<(NEXP * DDIM * RDIM + 255) / 256, 256>>>(Ag, Au, AgT, AuT);
    router_kernel<<<NTOK / 8, 256>>>(x, rw, idx, logits);
    lora_gemm_kernel<<<dim3(ERD / 128, NTOK / 128), 256>>>(x, AgT, idx, tgh, tgl);
    lora_gemm_kernel<<<dim3(ERD / 128, NTOK / 128), 256>>>(x, AuT, idx, tuh, tul);

    // big GEMMs (bf16x3 on mma.sync)
    mma_gemm<KGATE, DDIM, IDIM, 0>
        <<<dim3(IDIM / 128, NTOK / 128), 256, MM_SMEM>>>(
            xh, xl, tgh, tgl, WgTh, WgTl, nullptr, G, nullptr, nullptr);
    mma_gemm<KGATE, DDIM, IDIM, 1>
        <<<dim3(IDIM / 128, NTOK / 128), 256, MM_SMEM>>>(
            xh, xl, tuh, tul, WuTh, WuTl, G, nullptr, Hh, Hl);
    mma_gemm<IDIM, IDIM, DDIM, 0>
        <<<dim3(DDIM / 128, NTOK / 128), 256, MM_SMEM>>>(
            Hh, Hl, nullptr, nullptr, WdTh, WdTl, nullptr, out, nullptr, nullptr);
}

// round 16
// speedup vs baseline: 2.3868x; 1.0382x over previous
#include <cuda_runtime.h>
#include <cuda_bf16.h>

typedef unsigned int u32;
typedef unsigned long long u64;
typedef __nv_bfloat16 bf16;

#define NTOK 8192   // B*T
#define DDIM 2048
#define NEXP 8
#define IDIM 6144
#define RDIM 32
#define ERD  256    // NEXP*RDIM
#define KGATE (DDIM + ERD)   // 2304

// ---------------- scratch ---------------------------------------------------------
__device__ int   g_idx[NTOK];
__device__ float g_G[(size_t)NTOK * IDIM];
__device__ float g_logits_scratch[NTOK * NEXP];
// bf16 hi/lo operands
__device__ bf16 g_xh[(size_t)NTOK * DDIM];
__device__ bf16 g_xl[(size_t)NTOK * DDIM];
__device__ bf16 g_tgh[NTOK * ERD];
__device__ bf16 g_tgl[NTOK * ERD];
__device__ bf16 g_tuh[NTOK * ERD];
__device__ bf16 g_tul[NTOK * ERD];
__device__ bf16 g_Hh[(size_t)NTOK * IDIM];
__device__ bf16 g_Hl[(size_t)NTOK * IDIM];
// LoRA A transposed + split: [E*R, D] K-major
__device__ bf16 g_ATgh[ERD * DDIM];
__device__ bf16 g_ATgl[ERD * DDIM];
__device__ bf16 g_ATuh[ERD * DDIM];
__device__ bf16 g_ATul[ERD * DDIM];
// transposed + hi/lo-split weights: [N, Ktot] K-major
__device__ bf16 g_WgTh[(size_t)IDIM * KGATE];
__device__ bf16 g_WgTl[(size_t)IDIM * KGATE];
__device__ bf16 g_WuTh[(size_t)IDIM * KGATE];
__device__ bf16 g_WuTl[(size_t)IDIM * KGATE];
__device__ bf16 g_WdTh[(size_t)DDIM * IDIM];
__device__ bf16 g_WdTl[(size_t)DDIM * IDIM];

// ---------------- helpers ---------------------------------------------------------
__device__ __forceinline__ u32 s2u(const void* p) {
    u32 a;
    asm("{ .reg .u64 t; cvta.to.shared.u64 t, %1; cvt.u32.u64 %0, t; }" : "=r"(a) : "l"(p));
    return a;
}
// pack two fp32 -> bf16x2 (a -> low half, b -> high half)
__device__ __forceinline__ u32 cvt2(float a, float b) {
    u32 r;
    asm("cvt.rn.bf16x2.f32 %0, %1, %2;" : "=r"(r) : "f"(b), "f"(a));
    return r;
}
// split 2 floats into hi bf16x2 + lo bf16x2
__device__ __forceinline__ void split2(float a, float b, u32& h, u32& l) {
    h = cvt2(a, b);
    float fa = __uint_as_float(h << 16);
    float fb = __uint_as_float(h & 0xffff0000u);
    l = cvt2(a - fa, b - fb);
}
__device__ __forceinline__ void cpa(u32 d, const void* s) {
    asm volatile("cp.async.cg.shared.global [%0], [%1], 16;" :: "r"(d), "l"(s));
}
__device__ __forceinline__ void cp_commit() {
    asm volatile("cp.async.commit_group;" ::: "memory");
}
__device__ __forceinline__ void cp_wait1() {
    asm volatile("cp.async.wait_group 1;" ::: "memory");
}
__device__ __forceinline__ void ldm_x4(u32& r0, u32& r1, u32& r2, u32& r3, u32 a) {
    asm volatile("ldmatrix.sync.aligned.m8n8.x4.shared.b16 {%0,%1,%2,%3}, [%4];"
                 : "=r"(r0), "=r"(r1), "=r"(r2), "=r"(r3) : "r"(a));
}
__device__ __forceinline__ void mma_bf16(float* d, const u32* a, u32 b0, u32 b1) {
    asm volatile(
        "mma.sync.aligned.m16n8k16.row.col.f32.bf16.bf16.f32 "
        "{%0,%1,%2,%3}, {%4,%5,%6,%7}, {%8,%9}, {%0,%1,%2,%3};"
        : "+f"(d[0]), "+f"(d[1]), "+f"(d[2]), "+f"(d[3])
        : "r"(a[0]), "r"(a[1]), "r"(a[2]), "r"(a[3]), "r"(b0), "r"(b1));
}

// ---------------- router ----------------------------------------------------------
__global__ void router_kernel(const float* __restrict__ x,
                              const float* __restrict__ rw,
                              int* __restrict__ idx,
                              float* __restrict__ logits) {
    int gwarp = (blockIdx.x * blockDim.x + threadIdx.x) >> 5;
    int lane = threadIdx.x & 31;
    if (gwarp >= NTOK) return;
    const float* xp = x + (size_t)gwarp * DDIM;
    float acc[NEXP];
#pragma unroll
    for (int e = 0; e < NEXP; e++) acc[e] = 0.f;
    for (int d = lane; d < DDIM; d += 32) {
        float xv = xp[d];
        const float4* w4 = reinterpret_cast<const float4*>(rw + (size_t)d * NEXP);
        float4 w0 = w4[0], w1 = w4[1];
        acc[0] += xv * w0.x; acc[1] += xv * w0.y;
        acc[2] += xv * w0.z; acc[3] += xv * w0.w;
        acc[4] += xv * w1.x; acc[5] += xv * w1.y;
        acc[6] += xv * w1.z; acc[7] += xv * w1.w;
    }
#pragma unroll
    for (int e = 0; e < NEXP; e++) {
#pragma unroll
        for (int off = 16; off > 0; off >>= 1)
            acc[e] += __shfl_xor_sync(0xffffffffu, acc[e], off);
    }
    if (lane == 0) {
        int best = 0; float bv = acc[0];
#pragma unroll
        for (int e = 1; e < NEXP; e++)
            if (acc[e] > bv) { bv = acc[e]; best = e; }
        idx[gwarp] = best;
#pragma unroll
        for (int e = 0; e < NEXP; e++) logits[gwarp * NEXP + e] = acc[e];
    }
}

// ------------ weight transpose + bf16 hi/lo split: src [K,N] -> dst [N,Ktot] ------
__global__ void tconv_kernel(const float* __restrict__ src, int N, int ktot, int koff,
                             bf16* __restrict__ dh, bf16* __restrict__ dl) {
    __shared__ float t[32][33];
    int n0 = blockIdx.x * 32, k0 = blockIdx.y * 32;
    int tx = threadIdx.x, ty = threadIdx.y;   // 32 x 8
#pragma unroll
    for (int j = 0; j < 32; j += 8)
        t[ty + j][tx] = src[(size_t)(k0 + ty + j) * N + n0 + tx];
    __syncthreads();
#pragma unroll
    for (int j = 0; j < 32; j += 8) {
        int n = n0 + ty + j, k = k0 + tx;
        float v = t[tx][ty + j];
        bf16 h = __float2bfloat16(v);
        float hf = __bfloat162float(h);
        bf16 l = __float2bfloat16(v - hf);
        size_t o = (size_t)n * ktot + koff + k;
        dh[o] = h; dl[o] = l;
    }
}

// ------- LoRA A: [E, D, R] fp32 -> [E*R, D] bf16 hi/lo (K-major), both tensors ----
__global__ void aconv_kernel(const float* __restrict__ Ag, const float* __restrict__ Au,
                             bf16* __restrict__ gh, bf16* __restrict__ gl,
                             bf16* __restrict__ uh, bf16* __restrict__ ul) {
    __shared__ float tg_[32][33], tu_[32][33];
    int e = blockIdx.y;           // 0..7
    int d0 = blockIdx.x * 32;     // 0..63 blocks
    int tx = threadIdx.x, ty = threadIdx.y;  // 32 x 8
#pragma unroll
    for (int j = 0; j < 32; j += 8) {
        size_t src = ((size_t)e * DDIM + d0 + ty + j) * RDIM + tx;
        tg_[ty + j][tx] = Ag[src];
        tu_[ty + j][tx] = Au[src];
    }
    __syncthreads();
#pragma unroll
    for (int j = 0; j < 32; j += 8) {
        int r = ty + j;
        size_t o = (size_t)(e * RDIM + r) * DDIM + d0 + tx;
        float v = tg_[tx][r];
        bf16 h = __float2bfloat16(v);
        bf16 l = __float2bfloat16(v - __bfloat162float(h));
        gh[o] = h; gl[o] = l;
        v = tu_[tx][r];
        h = __float2bfloat16(v);
        l = __float2bfloat16(v - __bfloat162float(h));
        uh[o] = h; ul[o] = l;
    }
}

// ---------------- convert x fp32 -> bf16 hi/lo -----------------------------------
__global__ void cvt_x_kernel(const float4* __restrict__ src,
                             u32* __restrict__ dh, u32* __restrict__ dl) {
    int i = blockIdx.x * blockDim.x + threadIdx.x;  // group of 4 elements
    float4 v = src[i];
    u32 h0, l0, h1, l1;
    split2(v.x, v.y, h0, l0);
    split2(v.z, v.w, h1, l1);
    dh[i * 2] = h0; dh[i * 2 + 1] = h1;
    dl[i * 2] = l0; dl[i * 2 + 1] = l1;
}

// ---------------- bf16x3 GEMM on mma.sync (HMMA) ---------------------------------
// C[M, ND] = concat_K(A1[M,K1], A2[M,KTOT-K1]) @ B^T.  All operands bf16 hi/lo.
// MODE 0: store fp32 to outF.
// MODE 1: v = silu(Gprev)*acc, store bf16 hi/lo.
// MODE 3: mask to token's expert column block (32 cols), store bf16 hi/lo.
// CTA 128x128, 256 thr (8 warps = 2M x 4N, warp tile 64x32), BK=32, 3-stage cp.async.
// MMA schedule is pass-major (hh, hl, lh) so each accumulator's reuse distance is
// 16 MMAs — no RAW stall against HMMA latency.
#define MM_STAGE 40960
#define MM_SMEM  (3 * MM_STAGE)   // 120 KB

template<int KTOT, int K1, int ND, int MODE>
__global__ void __launch_bounds__(256, 1)
mma_gemm(const bf16* __restrict__ A1h, const bf16* __restrict__ A1l,
         const bf16* __restrict__ A2h, const bf16* __restrict__ A2l,
         const bf16* __restrict__ Bh,  const bf16* __restrict__ Bl,
         const float* __restrict__ Gprev, const int* __restrict__ idxp,
         float* __restrict__ outF, bf16* __restrict__ outH, bf16* __restrict__ outL) {
    constexpr int NC = KTOT / 32;
    extern __shared__ __align__(128) char smem[];
    const u32 sb = s2u(smem);
    const int tid = threadIdx.x, lane = tid & 31, wid = tid >> 5;
    const int warp_m = wid >> 2, warp_n = wid & 3;
    const int row0 = blockIdx.y * 128, col0 = blockIdx.x * 128;

    // per-thread ldmatrix offsets (row stride 80B)
    const u32 aoff = (u32)((warp_m * 64 + (lane & 15)) * 80 + ((lane >> 4) << 4));
    const u32 boff = (u32)((warp_n * 32 + (lane & 7) + ((lane >> 4) << 3)) * 80
                           + (((lane >> 3) & 1) << 4));

    float acc[4][4][4];
#pragma unroll
    for (int a = 0; a < 4; a++)
#pragma unroll
        for (int b = 0; b < 4; b++)
#pragma unroll
            for (int r = 0; r < 4; r++) acc[a][b][r] = 0.f;

    auto load_stage = [&](int c) {
        int kc = c * 32;
        const bf16 *ah, *al; int kst, ac;
        if (K1 == KTOT || kc < K1) { ah = A1h; al = A1l; kst = K1; ac = kc; }
        else { ah = A2h; al = A2l; kst = KTOT - K1; ac = kc - K1; }
        u32 st = sb + (u32)(c % 3) * MM_STAGE;
#pragma unroll
        for (int i = 0; i < 2; i++) {
            int ci = tid + i * 256, r = ci >> 2, q = ci & 3;
            u32 d = st + (u32)(r * 80 + q * 16);
            size_t go = (size_t)(row0 + r) * kst + ac + q * 8;
            cpa(d,         ah + go);
            cpa(d + 10240, al + go);
            size_t gb = (size_t)(col0 + r) * KTOT + kc + q * 8;
            cpa(d + 20480, Bh + gb);
            cpa(d + 30720, Bl + gb);
        }
    };

    load_stage(0); cp_commit();
    load_stage(1); cp_commit();

    for (int c = 0; c < NC; c++) {
        cp_wait1();
        __syncthreads();
        if (c + 2 < NC) load_stage(c + 2);
        cp_commit();

        u32 st = sb + (u32)(c % 3) * MM_STAGE;
#pragma unroll
        for (int kk = 0; kk < 2; kk++) {
            u32 afh[4][4], afl[4][4], bfh[2][4], bfl[2][4];
#pragma unroll
            for (int nt = 0; nt < 2; nt++) {
                u32 b = st + 20480 + boff + (u32)(nt * 16 * 80 + kk * 32);
                ldm_x4(bfh[nt][0], bfh[nt][1], bfh[nt][2], bfh[nt][3], b);
                ldm_x4(bfl[nt][0], bfl[nt][1], bfl[nt][2], bfl[nt][3], b + 10240);
            }
#pragma unroll
            for (int mt = 0; mt < 4; mt++) {
                u32 a = st + aoff + (u32)(mt * 16 * 80 + kk * 32);
                ldm_x4(afh[mt][0], afh[mt][1], afh[mt][2], afh[mt][3], a);
                ldm_x4(afl[mt][0], afl[mt][1], afl[mt][2], afl[mt][3], a + 10240);
            }
            // pass-major: hh, hl, lh — acc reuse distance = 16 MMAs
#pragma unroll
            for (int p = 0; p < 3; p++) {
#pragma unroll
                for (int mt = 0; mt < 4; mt++) {
                    const u32* af = (p == 2) ? afl[mt] : afh[mt];
#pragma unroll
                    for (int nt = 0; nt < 2; nt++) {
                        const u32* bf = (p == 1) ? bfl[nt] : bfh[nt];
                        mma_bf16(acc[mt][nt * 2 + 0], af, bf[0], bf[1]);
                        mma_bf16(acc[mt][nt * 2 + 1], af, bf[2], bf[3]);
                    }
                }
            }
        }
    }

    // epilogue
    const int rw0 = row0 + warp_m * 64 + (lane >> 2);
    const int cw0 = col0 + warp_n * 32 + (lane & 3) * 2;
#pragma unroll
    for (int mt = 0; mt < 4; mt++)
#pragma unroll
        for (int n8 = 0; n8 < 4; n8++) {
            float* d = acc[mt][n8];
            int row = rw0 + mt * 16;
            int col = cw0 + n8 * 8;
#pragma unroll
            for (int h = 0; h < 2; h++) {   // h=0: rows r, h=1: r+8
                int rr = row + h * 8;
                float v0 = d[h * 2 + 0], v1 = d[h * 2 + 1];
                size_t o = (size_t)rr * ND + col;
                if (MODE == 0) {
                    *reinterpret_cast<float2*>(outF + o) = make_float2(v0, v1);
                } else if (MODE == 1) {
                    float2 g = *reinterpret_cast<const float2*>(Gprev + o);
                    v0 *= g.x / (1.f + __expf(-g.x));
                    v1 *= g.y / (1.f + __expf(-g.y));
                    u32 hh, ll;
                    split2(v0, v1, hh, ll);
                    *reinterpret_cast<u32*>(outH + o) = hh;
                    *reinterpret_cast<u32*>(outL + o) = ll;
                } else {  // MODE 3: expert-column mask
                    u32 hh = 0, ll = 0;
                    if (idxp[rr] == (col >> 5)) split2(v0, v1, hh, ll);
                    *reinterpret_cast<u32*>(outH + o) = hh;
                    *reinterpret_cast<u32*>(outL + o) = ll;
                }
            }
        }
}

// ---------------- launch ----------------------------------------------------------
extern "C" void kernel_launch(void* const* d_in, const int* in_sizes, int n_in,
                              void* d_out, int out_size) {
    const float* x  = (const float*)d_in[0];
    const float* rw = (const float*)d_in[1];
    const float* Ag = (const float*)d_in[2];
    const float* Bg = (const float*)d_in[3];   // [E,R,I] == [256, 6144]
    const float* Au = (const float*)d_in[4];
    const float* Bu = (const float*)d_in[5];
    const float* Wg = (const float*)d_in[6];
    const float* Wu = (const float*)d_in[7];
    const float* Wd = (const float*)d_in[8];
    float* out = (float*)d_out;

    void* p;
    cudaGetSymbolAddress(&p, g_idx);            int*   idx = (int*)p;
    cudaGetSymbolAddress(&p, g_G);              float* G   = (float*)p;
    cudaGetSymbolAddress(&p, g_logits_scratch); float* lsc = (float*)p;
    cudaGetSymbolAddress(&p, g_xh);   bf16* xh  = (bf16*)p;
    cudaGetSymbolAddress(&p, g_xl);   bf16* xl  = (bf16*)p;
    cudaGetSymbolAddress(&p, g_tgh);  bf16* tgh = (bf16*)p;
    cudaGetSymbolAddress(&p, g_tgl);  bf16* tgl = (bf16*)p;
    cudaGetSymbolAddress(&p, g_tuh);  bf16* tuh = (bf16*)p;
    cudaGetSymbolAddress(&p, g_tul);  bf16* tul = (bf16*)p;
    cudaGetSymbolAddress(&p, g_Hh);   bf16* Hh  = (bf16*)p;
    cudaGetSymbolAddress(&p, g_Hl);   bf16* Hl  = (bf16*)p;
    cudaGetSymbolAddress(&p, g_ATgh); bf16* ATgh = (bf16*)p;
    cudaGetSymbolAddress(&p, g_ATgl); bf16* ATgl = (bf16*)p;
    cudaGetSymbolAddress(&p, g_ATuh); bf16* ATuh = (bf16*)p;
    cudaGetSymbolAddress(&p, g_ATul); bf16* ATul = (bf16*)p;
    cudaGetSymbolAddress(&p, g_WgTh); bf16* WgTh = (bf16*)p;
    cudaGetSymbolAddress(&p, g_WgTl); bf16* WgTl = (bf16*)p;
    cudaGetSymbolAddress(&p, g_WuTh); bf16* WuTh = (bf16*)p;
    cudaGetSymbolAddress(&p, g_WuTl); bf16* WuTl = (bf16*)p;
    cudaGetSymbolAddress(&p, g_WdTh); bf16* WdTh = (bf16*)p;
    cudaGetSymbolAddress(&p, g_WdTl); bf16* WdTl = (bf16*)p;

    const long long down_elems = (long long)NTOK * DDIM;
    float* logits = ((long long)out_size >= down_elems + (long long)NTOK * NEXP)
                        ? (out + down_elems) : lsc;

    cudaFuncSetAttribute(mma_gemm<DDIM, DDIM, ERD, 3>,
                         cudaFuncAttributeMaxDynamicSharedMemorySize, MM_SMEM);
    cudaFuncSetAttribute(mma_gemm<KGATE, DDIM, IDIM, 0>,
                         cudaFuncAttributeMaxDynamicSharedMemorySize, MM_SMEM);
    cudaFuncSetAttribute(mma_gemm<KGATE, DDIM, IDIM, 1>,
                         cudaFuncAttributeMaxDynamicSharedMemorySize, MM_SMEM);
    cudaFuncSetAttribute(mma_gemm<IDIM, IDIM, DDIM, 0>,
                         cudaFuncAttributeMaxDynamicSharedMemorySize, MM_SMEM);

    // weight prep: transpose + hi/lo split into combined [N, Ktot]
    dim3 tb32(32, 8);
    tconv_kernel<<<dim3(IDIM / 32, DDIM / 32), tb32>>>(Wg, IDIM, KGATE, 0,    WgTh, WgTl);
    tconv_kernel<<<dim3(IDIM / 32, ERD  / 32), tb32>>>(Bg, IDIM, KGATE, DDIM, WgTh, WgTl);
    tconv_kernel<<<dim3(IDIM / 32, DDIM / 32), tb32>>>(Wu, IDIM, KGATE, 0,    WuTh, WuTl);
    tconv_kernel<<<dim3(IDIM / 32, ERD  / 32), tb32>>>(Bu, IDIM, KGATE, DDIM, WuTh, WuTl);
    tconv_kernel<<<dim3(DDIM / 32, IDIM / 32), tb32>>>(Wd, DDIM, IDIM,  0,    WdTh, WdTl);
    aconv_kernel<<<dim3(DDIM / 32, NEXP), tb32>>>(Ag, Au, ATgh, ATgl, ATuh, ATul);

    // activations: x -> bf16 hi/lo
    cvt_x_kernel<<<(NTOK * DDIM / 4) / 256, 256>>>(
        reinterpret_cast<const float4*>(x), (u32*)xh, (u32*)xl);

    // router
    router_kernel<<<NTOK / 8, 256>>>(x, rw, idx, logits);

    // LoRA activations on MMA (masked, bf16 hi/lo out)
    mma_gemm<DDIM, DDIM, ERD, 3>
        <<<dim3(ERD / 128, NTOK / 128), 256, MM_SMEM>>>(
            xh, xl, nullptr, nullptr, ATgh, ATgl, nullptr, idx, nullptr, tgh, tgl);
    mma_gemm<DDIM, DDIM, ERD, 3>
        <<<dim3(ERD / 128, NTOK / 128), 256, MM_SMEM>>>(
            xh, xl, nullptr, nullptr, ATuh, ATul, nullptr, idx, nullptr, tuh, tul);

    // big GEMMs (bf16x3 on mma.sync)
    mma_gemm<KGATE, DDIM, IDIM, 0>
        <<<dim3(IDIM / 128, NTOK / 128), 256, MM_SMEM>>>(
            xh, xl, tgh, tgl, WgTh, WgTl, nullptr, nullptr, G, nullptr, nullptr);
    mma_gemm<KGATE, DDIM, IDIM, 1>
        <<<dim3(IDIM / 128, NTOK / 128), 256, MM_SMEM>>>(
            xh, xl, tuh, tul, WuTh, WuTl, G, nullptr, nullptr, Hh, Hl);
    mma_gemm<IDIM, IDIM, DDIM, 0>
        <<<dim3(DDIM / 128, NTOK / 128), 256, MM_SMEM>>>(
            Hh, Hl, nullptr, nullptr, WdTh, WdTl, nullptr, nullptr, out, nullptr, nullptr);
}

// round 17
// speedup vs baseline: 2.4043x; 1.0073x over previous
#include <cuda_runtime.h>
#include <cuda_bf16.h>
#include <cuda_fp16.h>

typedef unsigned int u32;
typedef unsigned long long u64;

#define NTOK 8192   // B*T
#define DDIM 2048
#define NEXP 8
#define IDIM 6144
#define RDIM 32
#define ERD  256    // NEXP*RDIM
#define KGATE (DDIM + ERD)   // 2304

#define LSCALE 2048.0f
#define LINV   (1.0f / 2048.0f)

// ---------------- scratch ---------------------------------------------------------
__device__ int    g_idx[NTOK];
__device__ float  g_G[(size_t)NTOK * IDIM];
__device__ float  g_logits_scratch[NTOK * NEXP];
// fp16 hi + scaled-lo operands
__device__ __half g_xh[(size_t)NTOK * DDIM];
__device__ __half g_xl[(size_t)NTOK * DDIM];
__device__ __half g_tgh[NTOK * ERD];
__device__ __half g_tgl[NTOK * ERD];
__device__ __half g_tuh[NTOK * ERD];
__device__ __half g_tul[NTOK * ERD];
__device__ __half g_Hh[(size_t)NTOK * IDIM];
__device__ __half g_Hl[(size_t)NTOK * IDIM];
// LoRA A transposed + split: [E*R, D] K-major
__device__ __half g_ATgh[ERD * DDIM];
__device__ __half g_ATgl[ERD * DDIM];
__device__ __half g_ATuh[ERD * DDIM];
__device__ __half g_ATul[ERD * DDIM];
// transposed + hi/lo-split weights: [N, Ktot] K-major
__device__ __half g_WgTh[(size_t)IDIM * KGATE];
__device__ __half g_WgTl[(size_t)IDIM * KGATE];
__device__ __half g_WuTh[(size_t)IDIM * KGATE];
__device__ __half g_WuTl[(size_t)IDIM * KGATE];
__device__ __half g_WdTh[(size_t)DDIM * IDIM];
__device__ __half g_WdTl[(size_t)DDIM * IDIM];

// ---------------- helpers ---------------------------------------------------------
__device__ __forceinline__ u32 s2u(const void* p) {
    u32 a;
    asm("{ .reg .u64 t; cvta.to.shared.u64 t, %1; cvt.u32.u64 %0, t; }" : "=r"(a) : "l"(p));
    return a;
}
// split 2 floats -> fp16x2 hi + fp16x2 scaled-lo
__device__ __forceinline__ void splitf(float a, float b, u32& h, u32& l) {
    __half2 h2 = __floats2half2_rn(a, b);
    float fa = __half2float(__low2half(h2));
    float fb = __half2float(__high2half(h2));
    __half2 l2 = __floats2half2_rn((a - fa) * LSCALE, (b - fb) * LSCALE);
    h = *reinterpret_cast<u32*>(&h2);
    l = *reinterpret_cast<u32*>(&l2);
}
__device__ __forceinline__ void cpa(u32 d, const void* s) {
    asm volatile("cp.async.cg.shared.global [%0], [%1], 16;" :: "r"(d), "l"(s));
}
__device__ __forceinline__ void cp_commit() {
    asm volatile("cp.async.commit_group;" ::: "memory");
}
__device__ __forceinline__ void cp_wait2() {
    asm volatile("cp.async.wait_group 2;" ::: "memory");
}
__device__ __forceinline__ void ldm_x4(u32& r0, u32& r1, u32& r2, u32& r3, u32 a) {
    asm volatile("ldmatrix.sync.aligned.m8n8.x4.shared.b16 {%0,%1,%2,%3}, [%4];"
                 : "=r"(r0), "=r"(r1), "=r"(r2), "=r"(r3) : "r"(a));
}
// fp16 inputs, fp32 accumulate
__device__ __forceinline__ void mma_f32a(float* d, const u32* a, u32 b0, u32 b1) {
    asm volatile(
        "mma.sync.aligned.m16n8k16.row.col.f32.f16.f16.f32 "
        "{%0,%1,%2,%3}, {%4,%5,%6,%7}, {%8,%9}, {%0,%1,%2,%3};"
        : "+f"(d[0]), "+f"(d[1]), "+f"(d[2]), "+f"(d[3])
        : "r"(a[0]), "r"(a[1]), "r"(a[2]), "r"(a[3]), "r"(b0), "r"(b1));
}
// fp16 inputs, fp16 accumulate (2x rate where supported)
__device__ __forceinline__ void mma_f16a(u32* d, const u32* a, u32 b0, u32 b1) {
    asm volatile(
        "mma.sync.aligned.m16n8k16.row.col.f16.f16.f16.f16 "
        "{%0,%1}, {%2,%3,%4,%5}, {%6,%7}, {%0,%1};"
        : "+r"(d[0]), "+r"(d[1])
        : "r"(a[0]), "r"(a[1]), "r"(a[2]), "r"(a[3]), "r"(b0), "r"(b1));
}

// ---------------- router ----------------------------------------------------------
__global__ void router_kernel(const float* __restrict__ x,
                              const float* __restrict__ rw,
                              int* __restrict__ idx,
                              float* __restrict__ logits) {
    int gwarp = (blockIdx.x * blockDim.x + threadIdx.x) >> 5;
    int lane = threadIdx.x & 31;
    if (gwarp >= NTOK) return;
    const float* xp = x + (size_t)gwarp * DDIM;
    float acc[NEXP];
#pragma unroll
    for (int e = 0; e < NEXP; e++) acc[e] = 0.f;
    for (int d = lane; d < DDIM; d += 32) {
        float xv = xp[d];
        const float4* w4 = reinterpret_cast<const float4*>(rw + (size_t)d * NEXP);
        float4 w0 = w4[0], w1 = w4[1];
        acc[0] += xv * w0.x; acc[1] += xv * w0.y;
        acc[2] += xv * w0.z; acc[3] += xv * w0.w;
        acc[4] += xv * w1.x; acc[5] += xv * w1.y;
        acc[6] += xv * w1.z; acc[7] += xv * w1.w;
    }
#pragma unroll
    for (int e = 0; e < NEXP; e++) {
#pragma unroll
        for (int off = 16; off > 0; off >>= 1)
            acc[e] += __shfl_xor_sync(0xffffffffu, acc[e], off);
    }
    if (lane == 0) {
        int best = 0; float bv = acc[0];
#pragma unroll
        for (int e = 1; e < NEXP; e++)
            if (acc[e] > bv) { bv = acc[e]; best = e; }
        idx[gwarp] = best;
#pragma unroll
        for (int e = 0; e < NEXP; e++) logits[gwarp * NEXP + e] = acc[e];
    }
}

// ------------ weight transpose + fp16 hi/lo split: src [K,N] -> dst [N,Ktot] ------
__global__ void tconv_kernel(const float* __restrict__ src, int N, int ktot, int koff,
                             __half* __restrict__ dh, __half* __restrict__ dl) {
    __shared__ float t[32][33];
    int n0 = blockIdx.x * 32, k0 = blockIdx.y * 32;
    int tx = threadIdx.x, ty = threadIdx.y;   // 32 x 8
#pragma unroll
    for (int j = 0; j < 32; j += 8)
        t[ty + j][tx] = src[(size_t)(k0 + ty + j) * N + n0 + tx];
    __syncthreads();
#pragma unroll
    for (int j = 0; j < 32; j += 8) {
        int n = n0 + ty + j, k = k0 + tx;
        float v = t[tx][ty + j];
        __half h = __float2half_rn(v);
        __half l = __float2half_rn((v - __half2float(h)) * LSCALE);
        size_t o = (size_t)n * ktot + koff + k;
        dh[o] = h; dl[o] = l;
    }
}

// ------- LoRA A: [E, D, R] fp32 -> [E*R, D] fp16 hi/lo (K-major), both tensors ----
__global__ void aconv_kernel(const float* __restrict__ Ag, const float* __restrict__ Au,
                             __half* __restrict__ gh, __half* __restrict__ gl,
                             __half* __restrict__ uh, __half* __restrict__ ul) {
    __shared__ float tg_[32][33], tu_[32][33];
    int e = blockIdx.y;
    int d0 = blockIdx.x * 32;
    int tx = threadIdx.x, ty = threadIdx.y;  // 32 x 8
#pragma unroll
    for (int j = 0; j < 32; j += 8) {
        size_t src = ((size_t)e * DDIM + d0 + ty + j) * RDIM + tx;
        tg_[ty + j][tx] = Ag[src];
        tu_[ty + j][tx] = Au[src];
    }
    __syncthreads();
#pragma unroll
    for (int j = 0; j < 32; j += 8) {
        int r = ty + j;
        size_t o = (size_t)(e * RDIM + r) * DDIM + d0 + tx;
        float v = tg_[tx][r];
        __half h = __float2half_rn(v);
        gh[o] = h;
        gl[o] = __float2half_rn((v - __half2float(h)) * LSCALE);
        v = tu_[tx][r];
        h = __float2half_rn(v);
        uh[o] = h;
        ul[o] = __float2half_rn((v - __half2float(h)) * LSCALE);
    }
}

// ---------------- convert x fp32 -> fp16 hi/lo ------------------------------------
__global__ void cvt_x_kernel(const float4* __restrict__ src,
                             u32* __restrict__ dh, u32* __restrict__ dl) {
    int i = blockIdx.x * blockDim.x + threadIdx.x;
    float4 v = src[i];
    u32 h0, l0, h1, l1;
    splitf(v.x, v.y, h0, l0);
    splitf(v.z, v.w, h1, l1);
    dh[i * 2] = h0; dh[i * 2 + 1] = h1;
    dl[i * 2] = l0; dl[i * 2 + 1] = l1;
}

// ---------------- fp16x3 GEMM on mma.sync (HMMA) ----------------------------------
// C = concat_K(A1, A2) @ B^T.  Operands fp16 hi + scaled-lo (x2048).
// Pass 1 (hi*hi): fp32 accumulate.  Passes 2+3 (hi*lo_s, lo_s*hi): fp16 accumulate,
// merged at epilogue with x(1/2048).
// MODE 0: store fp32.  MODE 1: silu(Gprev)*acc -> fp16 hi/lo.  MODE 3: expert mask.
// CTA 128x128, 256 thr (8 warps = 2Mx4N, warp tile 64x32), BK=32, 4-stage cp.async.
#define MM_STAGE 40960
#define MM_SMEM  (4 * MM_STAGE)   // 160 KB

template<int KTOT, int K1, int ND, int MODE>
__global__ void __launch_bounds__(256, 1)
mma_gemm(const __half* __restrict__ A1h, const __half* __restrict__ A1l,
         const __half* __restrict__ A2h, const __half* __restrict__ A2l,
         const __half* __restrict__ Bh,  const __half* __restrict__ Bl,
         const float* __restrict__ Gprev, const int* __restrict__ idxp,
         float* __restrict__ outF, __half* __restrict__ outH, __half* __restrict__ outL) {
    constexpr int NC = KTOT / 32;
    extern __shared__ __align__(128) char smem[];
    const u32 sb = s2u(smem);
    const int tid = threadIdx.x, lane = tid & 31, wid = tid >> 5;
    const int warp_m = wid >> 2, warp_n = wid & 3;
    const int row0 = blockIdx.y * 128, col0 = blockIdx.x * 128;

    const u32 aoff = (u32)((warp_m * 64 + (lane & 15)) * 80 + ((lane >> 4) << 4));
    const u32 boff = (u32)((warp_n * 32 + (lane & 7) + ((lane >> 4) << 3)) * 80
                           + (((lane >> 3) & 1) << 4));

    float acc[4][4][4];        // fp32 accumulators (hi*hi)
    u32   accC[4][4][2];       // fp16x2 accumulators (corrections), [mt][n8][pair]
#pragma unroll
    for (int a = 0; a < 4; a++)
#pragma unroll
        for (int b = 0; b < 4; b++) {
#pragma unroll
            for (int r = 0; r < 4; r++) acc[a][b][r] = 0.f;
            accC[a][b][0] = 0u; accC[a][b][1] = 0u;
        }

    auto load_stage = [&](int c) {
        int kc = c * 32;
        const __half *ah, *al; int kst, ac;
        if (K1 == KTOT || kc < K1) { ah = A1h; al = A1l; kst = K1; ac = kc; }
        else { ah = A2h; al = A2l; kst = KTOT - K1; ac = kc - K1; }
        u32 st = sb + (u32)(c & 3) * MM_STAGE;
#pragma unroll
        for (int i = 0; i < 2; i++) {
            int ci = tid + i * 256, r = ci >> 2, q = ci & 3;
            u32 d = st + (u32)(r * 80 + q * 16);
            size_t go = (size_t)(row0 + r) * kst + ac + q * 8;
            cpa(d,         ah + go);
            cpa(d + 10240, al + go);
            size_t gb = (size_t)(col0 + r) * KTOT + kc + q * 8;
            cpa(d + 20480, Bh + gb);
            cpa(d + 30720, Bl + gb);
        }
    };

    load_stage(0); cp_commit();
    load_stage(1); cp_commit();
    load_stage(2); cp_commit();

    for (int c = 0; c < NC; c++) {
        cp_wait2();
        __syncthreads();
        if (c + 3 < NC) load_stage(c + 3);
        cp_commit();

        u32 st = sb + (u32)(c & 3) * MM_STAGE;
#pragma unroll
        for (int kk = 0; kk < 2; kk++) {
            u32 afh[4][4], afl[4][4], bfh[2][4], bfl[2][4];
#pragma unroll
            for (int nt = 0; nt < 2; nt++) {
                u32 b = st + 20480 + boff + (u32)(nt * 16 * 80 + kk * 32);
                ldm_x4(bfh[nt][0], bfh[nt][1], bfh[nt][2], bfh[nt][3], b);
                ldm_x4(bfl[nt][0], bfl[nt][1], bfl[nt][2], bfl[nt][3], b + 10240);
            }
#pragma unroll
            for (int mt = 0; mt < 4; mt++) {
                u32 a = st + aoff + (u32)(mt * 16 * 80 + kk * 32);
                ldm_x4(afh[mt][0], afh[mt][1], afh[mt][2], afh[mt][3], a);
                ldm_x4(afl[mt][0], afl[mt][1], afl[mt][2], afl[mt][3], a + 10240);
            }
            // pass 1: hi*hi, fp32 acc
#pragma unroll
            for (int mt = 0; mt < 4; mt++)
#pragma unroll
                for (int nt = 0; nt < 2; nt++) {
                    mma_f32a(acc[mt][nt * 2 + 0], afh[mt], bfh[nt][0], bfh[nt][1]);
                    mma_f32a(acc[mt][nt * 2 + 1], afh[mt], bfh[nt][2], bfh[nt][3]);
                }
            // pass 2: hi * lo_s, fp16 acc
#pragma unroll
            for (int mt = 0; mt < 4; mt++)
#pragma unroll
                for (int nt = 0; nt < 2; nt++) {
                    mma_f16a(accC[mt][nt * 2 + 0], afh[mt], bfl[nt][0], bfl[nt][1]);
                    mma_f16a(accC[mt][nt * 2 + 1], afh[mt], bfl[nt][2], bfl[nt][3]);
                }
            // pass 3: lo_s * hi, fp16 acc
#pragma unroll
            for (int mt = 0; mt < 4; mt++)
#pragma unroll
                for (int nt = 0; nt < 2; nt++) {
                    mma_f16a(accC[mt][nt * 2 + 0], afl[mt], bfh[nt][0], bfh[nt][1]);
                    mma_f16a(accC[mt][nt * 2 + 1], afl[mt], bfh[nt][2], bfh[nt][3]);
                }
        }
    }

    // epilogue: merge corrections, apply MODE, store
    const int rw0 = row0 + warp_m * 64 + (lane >> 2);
    const int cw0 = col0 + warp_n * 32 + (lane & 3) * 2;
#pragma unroll
    for (int mt = 0; mt < 4; mt++)
#pragma unroll
        for (int n8 = 0; n8 < 4; n8++) {
            float* d = acc[mt][n8];
            int row = rw0 + mt * 16;
            int col = cw0 + n8 * 8;
#pragma unroll
            for (int h = 0; h < 2; h++) {   // h=0: row r, h=1: row r+8
                int rr = row + h * 8;
                __half2 ch2 = *reinterpret_cast<__half2*>(&accC[mt][n8][h]);
                float2 cf = __half22float2(ch2);
                float v0 = d[h * 2 + 0] + cf.x * LINV;
                float v1 = d[h * 2 + 1] + cf.y * LINV;
                size_t o = (size_t)rr * ND + col;
                if (MODE == 0) {
                    *reinterpret_cast<float2*>(outF + o) = make_float2(v0, v1);
                } else if (MODE == 1) {
                    float2 g = *reinterpret_cast<const float2*>(Gprev + o);
                    v0 *= g.x / (1.f + __expf(-g.x));
                    v1 *= g.y / (1.f + __expf(-g.y));
                    u32 hh, ll;
                    splitf(v0, v1, hh, ll);
                    *reinterpret_cast<u32*>(outH + o) = hh;
                    *reinterpret_cast<u32*>(outL + o) = ll;
                } else {  // MODE 3: expert-column mask
                    u32 hh = 0, ll = 0;
                    if (idxp[rr] == (col >> 5)) splitf(v0, v1, hh, ll);
                    *reinterpret_cast<u32*>(outH + o) = hh;
                    *reinterpret_cast<u32*>(outL + o) = ll;
                }
            }
        }
}

// ---------------- launch ----------------------------------------------------------
extern "C" void kernel_launch(void* const* d_in, const int* in_sizes, int n_in,
                              void* d_out, int out_size) {
    const float* x  = (const float*)d_in[0];
    const float* rw = (const float*)d_in[1];
    const float* Ag = (const float*)d_in[2];
    const float* Bg = (const float*)d_in[3];   // [E,R,I] == [256, 6144]
    const float* Au = (const float*)d_in[4];
    const float* Bu = (const float*)d_in[5];
    const float* Wg = (const float*)d_in[6];
    const float* Wu = (const float*)d_in[7];
    const float* Wd = (const float*)d_in[8];
    float* out = (float*)d_out;

    void* p;
    cudaGetSymbolAddress(&p, g_idx);            int*   idx = (int*)p;
    cudaGetSymbolAddress(&p, g_G);              float* G   = (float*)p;
    cudaGetSymbolAddress(&p, g_logits_scratch); float* lsc = (float*)p;
    cudaGetSymbolAddress(&p, g_xh);   __half* xh  = (__half*)p;
    cudaGetSymbolAddress(&p, g_xl);   __half* xl  = (__half*)p;
    cudaGetSymbolAddress(&p, g_tgh);  __half* tgh = (__half*)p;
    cudaGetSymbolAddress(&p, g_tgl);  __half* tgl = (__half*)p;
    cudaGetSymbolAddress(&p, g_tuh);  __half* tuh = (__half*)p;
    cudaGetSymbolAddress(&p, g_tul);  __half* tul = (__half*)p;
    cudaGetSymbolAddress(&p, g_Hh);   __half* Hh  = (__half*)p;
    cudaGetSymbolAddress(&p, g_Hl);   __half* Hl  = (__half*)p;
    cudaGetSymbolAddress(&p, g_ATgh); __half* ATgh = (__half*)p;
    cudaGetSymbolAddress(&p, g_ATgl); __half* ATgl = (__half*)p;
    cudaGetSymbolAddress(&p, g_ATuh); __half* ATuh = (__half*)p;
    cudaGetSymbolAddress(&p, g_ATul); __half* ATul = (__half*)p;
    cudaGetSymbolAddress(&p, g_WgTh); __half* WgTh = (__half*)p;
    cudaGetSymbolAddress(&p, g_WgTl); __half* WgTl = (__half*)p;
    cudaGetSymbolAddress(&p, g_WuTh); __half* WuTh = (__half*)p;
    cudaGetSymbolAddress(&p, g_WuTl); __half* WuTl = (__half*)p;
    cudaGetSymbolAddress(&p, g_WdTh); __half* WdTh = (__half*)p;
    cudaGetSymbolAddress(&p, g_WdTl); __half* WdTl = (__half*)p;

    const long long down_elems = (long long)NTOK * DDIM;
    float* logits = ((long long)out_size >= down_elems + (long long)NTOK * NEXP)
                        ? (out + down_elems) : lsc;

    cudaFuncSetAttribute(mma_gemm<DDIM, DDIM, ERD, 3>,
                         cudaFuncAttributeMaxDynamicSharedMemorySize, MM_SMEM);
    cudaFuncSetAttribute(mma_gemm<KGATE, DDIM, IDIM, 0>,
                         cudaFuncAttributeMaxDynamicSharedMemorySize, MM_SMEM);
    cudaFuncSetAttribute(mma_gemm<KGATE, DDIM, IDIM, 1>,
                         cudaFuncAttributeMaxDynamicSharedMemorySize, MM_SMEM);
    cudaFuncSetAttribute(mma_gemm<IDIM, IDIM, DDIM, 0>,
                         cudaFuncAttributeMaxDynamicSharedMemorySize, MM_SMEM);

    // weight prep: transpose + fp16 hi/lo split into combined [N, Ktot]
    dim3 tb32(32, 8);
    tconv_kernel<<<dim3(IDIM / 32, DDIM / 32), tb32>>>(Wg, IDIM, KGATE, 0,    WgTh, WgTl);
    tconv_kernel<<<dim3(IDIM / 32, ERD  / 32), tb32>>>(Bg, IDIM, KGATE, DDIM, WgTh, WgTl);
    tconv_kernel<<<dim3(IDIM / 32, DDIM / 32), tb32>>>(Wu, IDIM, KGATE, 0,    WuTh, WuTl);
    tconv_kernel<<<dim3(IDIM / 32, ERD  / 32), tb32>>>(Bu, IDIM, KGATE, DDIM, WuTh, WuTl);
    tconv_kernel<<<dim3(DDIM / 32, IDIM / 32), tb32>>>(Wd, DDIM, IDIM,  0,    WdTh, WdTl);
    aconv_kernel<<<dim3(DDIM / 32, NEXP), tb32>>>(Ag, Au, ATgh, ATgl, ATuh, ATul);

    // activations: x -> fp16 hi/lo
    cvt_x_kernel<<<(NTOK * DDIM / 4) / 256, 256>>>(
        reinterpret_cast<const float4*>(x), (u32*)xh, (u32*)xl);

    // router
    router_kernel<<<NTOK / 8, 256>>>(x, rw, idx, logits);

    // LoRA activations on MMA (masked, fp16 hi/lo out)
    mma_gemm<DDIM, DDIM, ERD, 3>
        <<<dim3(ERD / 128, NTOK / 128), 256, MM_SMEM>>>(
            xh, xl, nullptr, nullptr, ATgh, ATgl, nullptr, idx, nullptr, tgh, tgl);
    mma_gemm<DDIM, DDIM, ERD, 3>
        <<<dim3(ERD / 128, NTOK / 128), 256, MM_SMEM>>>(
            xh, xl, nullptr, nullptr, ATuh, ATul, nullptr, idx, nullptr, tuh, tul);

    // big GEMMs (fp16x3 on mma.sync, fp16-acc corrections)
    mma_gemm<KGATE, DDIM, IDIM, 0>
        <<<dim3(IDIM / 128, NTOK / 128), 256, MM_SMEM>>>(
            xh, xl, tgh, tgl, WgTh, WgTl, nullptr, nullptr, G, nullptr, nullptr);
    mma_gemm<KGATE, DDIM, IDIM, 1>
        <<<dim3(IDIM / 128, NTOK / 128), 256, MM_SMEM>>>(
            xh, xl, tuh, tul, WuTh, WuTl, G, nullptr, nullptr, Hh, Hl);
    mma_gemm<IDIM, IDIM, DDIM, 0>
        <<<dim3(DDIM / 128, NTOK / 128), 256, MM_SMEM>>>(
            Hh, Hl, nullptr, nullptr, WdTh, WdTl, nullptr, nullptr, out, nullptr, nullptr);
}